// round 16
// baseline (speedup 1.0000x reference)
#include <cuda_runtime.h>
#include <cuda_fp16.h>
#include <cstdint>
#include <cstddef>

#define THREADS 1024
#define NTILES  1024          // 65536 / 64
#define GRID    148
#define STEPS   12
#define KD      128
#define KK_STEPS 8

// ---- smem layout (bytes from dynamic base) ----
#define OFF_W    0            // 512 rows * 256B fp16 swizzled   = 131072
#define OFF_W2   131072       // 512 rows * 48B  [wx,wy,bz,0..]  =  24576
#define OFF_X2   155648       // 64 rows * 48B   [rx,ry,1,0..]   =   3072
#define OFF_X    158720       // 2 buf x (64 rows * 256B)        =  32768
#define XBUF_BYTES 16384
#define OFF_WHP  191488       // float[256]                      =   1024
#define OFF_PART 192512       // float[64][36]                   =   9216
#define OFF_BHP  201728       // float[2]                        =      8
#define SMEM_BYTES 201792

__device__ __forceinline__ uint32_t smem_u32(const void* p) {
    uint32_t a;
    asm("{ .reg .u64 t; cvta.to.shared.u64 t, %1; cvt.u32.u64 %0, t; }" : "=r"(a) : "l"(p));
    return a;
}
__device__ __forceinline__ uint32_t packh2(float lo, float hi) {
    uint32_t r; asm("cvt.rn.f16x2.f32 %0, %1, %2;" : "=r"(r) : "f"(hi), "f"(lo)); return r;
}
__device__ __forceinline__ float tanh_ap(float x) {
    float y; asm("tanh.approx.f32 %0, %1;" : "=f"(y) : "f"(x)); return y;
}
__device__ __forceinline__ float siga(float x) { return fmaf(tanh_ap(0.5f * x), 0.5f, 0.5f); }

#define LDSM_X4(r0, r1, r2, r3, addr)                                                  \
    asm volatile("ldmatrix.sync.aligned.m8n8.x4.shared.b16 {%0,%1,%2,%3}, [%4];"       \
                 : "=r"(r0), "=r"(r1), "=r"(r2), "=r"(r3) : "r"(addr))

#define MMA16816(d, a0, a1, a2, a3, b0, b1)                                            \
    asm volatile("mma.sync.aligned.m16n8k16.row.col.f32.f16.f16.f32 "                  \
                 "{%0,%1,%2,%3}, {%4,%5,%6,%7}, {%8,%9}, {%0,%1,%2,%3};"               \
                 : "+f"((d)[0]), "+f"((d)[1]), "+f"((d)[2]), "+f"((d)[3])              \
                 : "r"(a0), "r"(a1), "r"(a2), "r"(a3), "r"(b0), "r"(b1))

// swizzled byte offset within a 256B-row fp16 tile
__device__ __forceinline__ uint32_t swz_off(int r, int k) {
    return (uint32_t)(r * 256 + ((((k >> 3) ^ (r & 7)) << 4) | ((k & 7) * 2)));
}

__global__ __launch_bounds__(THREADS, 1)
void decoder_mma(const float* __restrict__ lpr, const float* __restrict__ h0,
                 const float* __restrict__ c0,
                 const float* __restrict__ w_ih, const float* __restrict__ w_hh,
                 const float* __restrict__ b_ih, const float* __restrict__ b_hh,
                 const float* __restrict__ w_se, const float* __restrict__ b_se,
                 const float* __restrict__ w_hp, const float* __restrict__ b_hp,
                 float2* __restrict__ out)
{
    extern __shared__ char S[];
    const uint32_t Sb = smem_u32(S);
    float* whp  = (float*)(S + OFF_WHP);
    float* part = (float*)(S + OFF_PART);   // [64][36]
    float* bhp  = (float*)(S + OFF_BHP);

    const int tid = threadIdx.x, lane = tid & 31, w = tid >> 5;
    const int mg = w & 1, ng = w >> 1;      // 2 M-groups x 16 N-groups, warp m32n32
    const int g4 = lane >> 2, c2 = (lane & 3) * 2;

    // ================= one-time prep =================
    // W col reorder: n = ng*32 + gate*8 + ul  ->  global gate row gate*128 + ng*8 + ul
    for (int i = tid; i < 512 * KD; i += THREADS) {
        int n = i >> 7, k = i & 127;
        int grow = ((n >> 3) & 3) * 128 + (n >> 5) * 8 + (n & 7);
        *(__half*)(S + OFF_W + swz_off(n, k)) = __float2half_rn(w_hh[grow * 128 + k]);
    }
    for (int i = tid; i < (24576 + 3072) / 4; i += THREADS)   // zero W2 + X2
        ((uint32_t*)(S + OFF_W2))[i] = 0;
    if (tid < 256) whp[tid] = w_hp[tid];
    if (tid < 2)   bhp[tid] = b_hp[tid];
    __syncthreads();
    for (int n = tid; n < 512; n += THREADS) {   // rank-2 folded dec_in weights + bias
        int grow = ((n >> 3) & 3) * 128 + (n >> 5) * 8 + (n & 7);
        float wx = 0.f, wy = 0.f, bz = b_ih[grow] + b_hh[grow];
        for (int e = 0; e < 64; e++) {
            float wv = w_ih[grow * 64 + e];
            wx = fmaf(wv, w_se[e * 2],     wx);
            wy = fmaf(wv, w_se[e * 2 + 1], wy);
            bz = fmaf(wv, b_se[e],         bz);
        }
        __half* w2r = (__half*)(S + OFF_W2 + n * 48);
        w2r[0] = __float2half_rn(wx);
        w2r[1] = __float2half_rn(wy);
        w2r[2] = __float2half_rn(bz);
    }
    if (tid < 64)   // X2 col 2 = constant 1.0 (multiplies bz)
        ((__half*)(S + OFF_X2 + tid * 48))[2] = __float2half_rn(1.0f);
    __syncthreads();

    // ldmatrix per-lane address components
    const uint32_t ax_     = (uint32_t)(lane & 7);
    const uint32_t asel    = (uint32_t)(lane >> 4);
    const uint32_t arowoff = (uint32_t)(mg * 32 + (lane & 15)) * 256;
    const uint32_t bdn     = (uint32_t)((lane & 7) + ((lane >> 4) << 3));
    const uint32_t bbase   = Sb + OFF_W + (uint32_t)(ng * 32 + bdn) * 256;
    const uint32_t bk_     = (uint32_t)((lane >> 3) & 1);
    const uint32_t w2base  = Sb + OFF_W2 + (uint32_t)(ng * 32 + bdn) * 48 + (bk_ << 4);
    const uint32_t x2base  = Sb + OFF_X2 + (uint32_t)(mg * 32 + (lane & 15)) * 48 + (asel << 4);

    // ================= persistent tile loop =================
    for (int tile = blockIdx.x; tile < NTILES; tile += gridDim.x) {
        const int pedb = tile * 64;
        __syncthreads();   // previous tile fully drained

        // ---- init: h0 -> X buffer 0, lpr -> X2, c0 -> regs ----
        for (int i = tid; i < 64 * 64; i += THREADS) {
            int r = i >> 6, kp = (i & 63) * 2;
            float2 hv = *(const float2*)(h0 + (size_t)(pedb + r) * 128 + kp);
            *(uint32_t*)(S + OFF_X + swz_off(r, kp)) = packh2(hv.x, hv.y);
        }
        if (tid < 64) {
            float2 lv = *(const float2*)(lpr + (size_t)(pedb + tid) * 2);
            *(uint32_t*)(S + OFF_X2 + tid * 48) = packh2(lv.x, lv.y);
        }
        float c_arr[8];   // [mt][e][row8]
#pragma unroll
        for (int mt = 0; mt < 2; mt++)
#pragma unroll
            for (int row8 = 0; row8 < 2; row8++) {
                int gp = pedb + mg * 32 + mt * 16 + g4 + row8 * 8;
                int U0 = ng * 8 + c2;
                float2 cv = *(const float2*)(c0 + (size_t)gp * 128 + U0);
                c_arr[mt * 4 + row8]     = cv.x;   // e=0
                c_arr[mt * 4 + 2 + row8] = cv.y;   // e=1
            }
        __syncthreads();

        int par = 0;
        // ================= 12 recurrent steps =================
        for (int st = 0; st < STEPS; st++) {
            const uint32_t abase = Sb + OFF_X + (uint32_t)par * XBUF_BYTES + arowoff;
            const uint32_t xw    = (uint32_t)(par ^ 1) * XBUF_BYTES;

            // ---- GEMM: gates = [h | rx,ry,1] @ [Whh | wx,wy,bz]^T ----
            float acc[2][4][4];   // [mt][gate][frag]
#pragma unroll
            for (int mt = 0; mt < 2; mt++)
#pragma unroll
                for (int nt = 0; nt < 4; nt++)
#pragma unroll
                    for (int j = 0; j < 4; j++) acc[mt][nt][j] = 0.f;

#pragma unroll
            for (int kk = 0; kk < KK_STEPS; kk++) {
                const uint32_t koff = (((uint32_t)(2 * kk) + asel) ^ ax_) << 4;
                uint32_t a0[4], a1[4];
                LDSM_X4(a0[0], a0[1], a0[2], a0[3], abase + koff);
                LDSM_X4(a1[0], a1[1], a1[2], a1[3], abase + 4096 + koff);
                const uint32_t bkoff = (((uint32_t)(2 * kk) + bk_) ^ ax_) << 4;
#pragma unroll
                for (int t2 = 0; t2 < 2; t2++) {
                    uint32_t b0, b1, b2, b3;
                    LDSM_X4(b0, b1, b2, b3, bbase + (uint32_t)t2 * 4096 + bkoff);
                    MMA16816(acc[0][2 * t2],     a0[0], a0[1], a0[2], a0[3], b0, b1);
                    MMA16816(acc[0][2 * t2 + 1], a0[0], a0[1], a0[2], a0[3], b2, b3);
                    MMA16816(acc[1][2 * t2],     a1[0], a1[1], a1[2], a1[3], b0, b1);
                    MMA16816(acc[1][2 * t2 + 1], a1[0], a1[1], a1[2], a1[3], b2, b3);
                }
            }
            {   // extra k16 step: rank-2 dec_in + bias (X2 @ W2^T)
                uint32_t a0[4], a1[4];
                LDSM_X4(a0[0], a0[1], a0[2], a0[3], x2base);
                LDSM_X4(a1[0], a1[1], a1[2], a1[3], x2base + 768);   // rows 16-31
#pragma unroll
                for (int t2 = 0; t2 < 2; t2++) {
                    uint32_t b0, b1, b2, b3;
                    LDSM_X4(b0, b1, b2, b3, w2base + (uint32_t)t2 * 768);
                    MMA16816(acc[0][2 * t2],     a0[0], a0[1], a0[2], a0[3], b0, b1);
                    MMA16816(acc[0][2 * t2 + 1], a0[0], a0[1], a0[2], a0[3], b2, b3);
                    MMA16816(acc[1][2 * t2],     a1[0], a1[1], a1[2], a1[3], b0, b1);
                    MMA16816(acc[1][2 * t2 + 1], a1[0], a1[1], a1[2], a1[3], b2, b3);
                }
            }

            // ---- epilogue: activations; h -> other X buf; rel partials ----
            float axs[2][2], ays[2][2];
#pragma unroll
            for (int mt = 0; mt < 2; mt++) {
                axs[mt][0] = ays[mt][0] = axs[mt][1] = ays[mt][1] = 0.f;
#pragma unroll
                for (int row8 = 0; row8 < 2; row8++) {
                    float hpair[2];
#pragma unroll
                    for (int e = 0; e < 2; e++) {
                        int reg = row8 * 2 + e;
                        float gi = acc[mt][0][reg];
                        float gf = acc[mt][1][reg];
                        float gg = acc[mt][2][reg];
                        float go = acc[mt][3][reg];
                        int ci = mt * 4 + e * 2 + row8;
                        float cc = siga(gf) * c_arr[ci] + siga(gi) * tanh_ap(gg);
                        c_arr[ci] = cc;
                        float h = siga(go) * tanh_ap(cc);
                        hpair[e] = h;
                        int ul = ng * 8 + c2 + e;
                        axs[mt][row8] = fmaf(h, whp[ul],       axs[mt][row8]);
                        ays[mt][row8] = fmaf(h, whp[128 + ul], ays[mt][row8]);
                    }
                    int r = mg * 32 + mt * 16 + g4 + row8 * 8;
                    *(uint32_t*)(S + OFF_X + xw + swz_off(r, ng * 8 + c2)) =
                        packh2(hpair[0], hpair[1]);
                }
            }
            // butterfly over the quad lanes (same peds, different units)
#pragma unroll
            for (int mt = 0; mt < 2; mt++)
#pragma unroll
                for (int row8 = 0; row8 < 2; row8++) {
                    float& ax = axs[mt][row8];
                    float& ay = ays[mt][row8];
                    ax += __shfl_xor_sync(~0u, ax, 1); ax += __shfl_xor_sync(~0u, ax, 2);
                    ay += __shfl_xor_sync(~0u, ay, 1); ay += __shfl_xor_sync(~0u, ay, 2);
                }
            if ((lane & 3) == 0) {
#pragma unroll
                for (int mt = 0; mt < 2; mt++)
#pragma unroll
                    for (int row8 = 0; row8 < 2; row8++) {
                        int r = mg * 32 + mt * 16 + g4 + row8 * 8;
                        *(float2*)(part + r * 36 + ng * 2) =
                            make_float2(axs[mt][row8], ays[mt][row8]);
                    }
            }
            __syncthreads();   // X + part complete

            // ---- reduce: rel = sum over 16 N-groups + b_hp; out; X2 ----
            if (tid < 64) {
                const float4* pr = (const float4*)(part + tid * 36);
                float4 q0 = pr[0], q1 = pr[1], q2 = pr[2], q3 = pr[3];
                float4 q4 = pr[4], q5 = pr[5], q6 = pr[6], q7 = pr[7];
                float rx = q0.x + q0.z + q1.x + q1.z + q2.x + q2.z + q3.x + q3.z +
                           q4.x + q4.z + q5.x + q5.z + q6.x + q6.z + q7.x + q7.z + bhp[0];
                float ry = q0.y + q0.w + q1.y + q1.w + q2.y + q2.w + q3.y + q3.w +
                           q4.y + q4.w + q5.y + q5.w + q6.y + q6.w + q7.y + q7.w + bhp[1];
                out[(size_t)st * 65536 + pedb + tid] = make_float2(rx, ry);
                *(uint32_t*)(S + OFF_X2 + tid * 48) = packh2(rx, ry);
            }
            __syncthreads();   // X2 ready for next step
            par ^= 1;
        }
    }
}

extern "C" void kernel_launch(void* const* d_in, const int* in_sizes, int n_in,
                              void* d_out, int out_size) {
    (void)in_sizes; (void)n_in; (void)out_size;
    const float* lpr  = (const float*)d_in[1];
    const float* h0   = (const float*)d_in[2];
    const float* c0   = (const float*)d_in[3];
    const float* w_ih = (const float*)d_in[4];
    const float* w_hh = (const float*)d_in[5];
    const float* b_ih = (const float*)d_in[6];
    const float* b_hh = (const float*)d_in[7];
    const float* w_se = (const float*)d_in[8];
    const float* b_se = (const float*)d_in[9];
    const float* w_hp = (const float*)d_in[10];
    const float* b_hp = (const float*)d_in[11];

    cudaFuncSetAttribute(decoder_mma, cudaFuncAttributeMaxDynamicSharedMemorySize, SMEM_BYTES);
    decoder_mma<<<GRID, THREADS, SMEM_BYTES>>>(lpr, h0, c0, w_ih, w_hh, b_ih, b_hh,
                                               w_se, b_se, w_hp, b_hp, (float2*)d_out);
}

// round 17
// speedup vs baseline: 1.1177x; 1.1177x over previous
#include <cuda_runtime.h>
#include <cuda_fp16.h>
#include <cstdint>
#include <cstddef>

#define THREADS 512
#define NPAIRS  1024          // 65536 / 64 peds per CTA-iteration
#define GRID    148
#define STEPS   12
#define KD      128
#define KK_STEPS 8

// ---- smem layout (bytes from dynamic base) ----
#define OFF_W    0            // 512 rows * 256B fp16 swizzled   = 131072
#define OFF_W2   131072       // 512 rows * 48B  [wx,wy,bz,0..]  =  24576
#define OFF_X2   155648       // 2 tile x 32 rows * 48B          =   3072
#define OFF_X    158720       // 2 tile x 2 buf x (32*256B)      =  32768
#define OFF_WHP  191488       // float[256]                      =   1024
#define OFF_PART 192512       // float[64][36]                   =   9216
#define OFF_BHP  201728       // float[2]                        =      8
#define SMEM_BYTES 201792

__device__ __forceinline__ uint32_t smem_u32(const void* p) {
    uint32_t a;
    asm("{ .reg .u64 t; cvta.to.shared.u64 t, %1; cvt.u32.u64 %0, t; }" : "=r"(a) : "l"(p));
    return a;
}
__device__ __forceinline__ uint32_t packh2(float lo, float hi) {
    uint32_t r; asm("cvt.rn.f16x2.f32 %0, %1, %2;" : "=r"(r) : "f"(hi), "f"(lo)); return r;
}
__device__ __forceinline__ float tanh_ap(float x) {
    float y; asm("tanh.approx.f32 %0, %1;" : "=f"(y) : "f"(x)); return y;
}
__device__ __forceinline__ float siga(float x) { return fmaf(tanh_ap(0.5f * x), 0.5f, 0.5f); }

#define LDSM_X4(r0, r1, r2, r3, addr)                                                  \
    asm volatile("ldmatrix.sync.aligned.m8n8.x4.shared.b16 {%0,%1,%2,%3}, [%4];"       \
                 : "=r"(r0), "=r"(r1), "=r"(r2), "=r"(r3) : "r"(addr))

#define MMA16816(d, a0, a1, a2, a3, b0, b1)                                            \
    asm volatile("mma.sync.aligned.m16n8k16.row.col.f32.f16.f16.f32 "                  \
                 "{%0,%1,%2,%3}, {%4,%5,%6,%7}, {%8,%9}, {%0,%1,%2,%3};"               \
                 : "+f"((d)[0]), "+f"((d)[1]), "+f"((d)[2]), "+f"((d)[3])              \
                 : "r"(a0), "r"(a1), "r"(a2), "r"(a3), "r"(b0), "r"(b1))

// swizzled byte offset within a 256B-row fp16 tile
__device__ __forceinline__ uint32_t swz_off(int r, int k) {
    return (uint32_t)(r * 256 + ((((k >> 3) ^ (r & 7)) << 4) | ((k & 7) * 2)));
}

__global__ __launch_bounds__(THREADS, 1)
void decoder_mma(const float* __restrict__ lpr, const float* __restrict__ h0,
                 const float* __restrict__ c0,
                 const float* __restrict__ w_ih, const float* __restrict__ w_hh,
                 const float* __restrict__ b_ih, const float* __restrict__ b_hh,
                 const float* __restrict__ w_se, const float* __restrict__ b_se,
                 const float* __restrict__ w_hp, const float* __restrict__ b_hp,
                 float2* __restrict__ out)
{
    extern __shared__ char S[];
    const uint32_t Sb = smem_u32(S);
    float* whp  = (float*)(S + OFF_WHP);
    float* part = (float*)(S + OFF_PART);   // [64][36]: rows 0-31 tile A, 32-63 tile B
    float* bhp  = (float*)(S + OFF_BHP);

    const int tid = threadIdx.x, lane = tid & 31;
    const int ng = tid >> 5;                // 16 N-groups; warp tile m32 x n32
    const int g4 = lane >> 2, c2 = (lane & 3) * 2;

    // ================= one-time prep =================
    // W reorder: n = ng*32 + gate*8 + ul  ->  global gate row gate*128 + ng*8 + ul
    for (int i = tid; i < 512 * KD; i += THREADS) {
        int n = i >> 7, k = i & 127;
        int grow = ((n >> 3) & 3) * 128 + (n >> 5) * 8 + (n & 7);
        *(__half*)(S + OFF_W + swz_off(n, k)) = __float2half_rn(w_hh[grow * 128 + k]);
    }
    for (int i = tid; i < (24576 + 3072) / 4; i += THREADS)   // zero W2 + X2
        ((uint32_t*)(S + OFF_W2))[i] = 0;
    if (tid < 256) whp[tid] = w_hp[tid];
    if (tid < 2)   bhp[tid] = b_hp[tid];
    __syncthreads();
    for (int n = tid; n < 512; n += THREADS) {   // rank-2 folded dec_in weights + bias
        int grow = ((n >> 3) & 3) * 128 + (n >> 5) * 8 + (n & 7);
        float wx = 0.f, wy = 0.f, bz = b_ih[grow] + b_hh[grow];
        for (int e = 0; e < 64; e++) {
            float wv = w_ih[grow * 64 + e];
            wx = fmaf(wv, w_se[e * 2],     wx);
            wy = fmaf(wv, w_se[e * 2 + 1], wy);
            bz = fmaf(wv, b_se[e],         bz);
        }
        __half* w2r = (__half*)(S + OFF_W2 + n * 48);
        w2r[0] = __float2half_rn(wx);
        w2r[1] = __float2half_rn(wy);
        w2r[2] = __float2half_rn(bz);
    }
    if (tid < 64)   // X2 col 2 = constant 1.0 (both tiles, 32 rows each)
        ((__half*)(S + OFF_X2 + tid * 48))[2] = __float2half_rn(1.0f);
    __syncthreads();

    // ldmatrix per-lane address components
    const uint32_t ax_     = (uint32_t)(lane & 7);
    const uint32_t asel    = (uint32_t)(lane >> 4);
    const uint32_t arowoff = (uint32_t)(lane & 15) * 256;
    const uint32_t bdn     = (uint32_t)((lane & 7) + ((lane >> 4) << 3));
    const uint32_t bbase   = Sb + OFF_W + (uint32_t)(ng * 32 + bdn) * 256;
    const uint32_t bk_     = (uint32_t)((lane >> 3) & 1);
    const uint32_t w2base  = Sb + OFF_W2 + (uint32_t)(ng * 32 + bdn) * 48 + (bk_ << 4);
    const uint32_t x2lane  = (uint32_t)(lane & 15) * 48 + (asel << 4);

    // ================= persistent pair loop =================
    for (int p = blockIdx.x; p < NPAIRS; p += gridDim.x) {
        __syncthreads();   // previous pair fully drained

        // ---- init: h0 -> X[t][0], lpr -> X2[t], c0 -> regs ----
        for (int i = tid; i < 64 * 64; i += THREADS) {
            int r = i >> 6, kp = (i & 63) * 2;   // r: 0-63 across both tiles
            float2 hv = *(const float2*)(h0 + (size_t)(p * 64 + r) * 128 + kp);
            *(uint32_t*)(S + OFF_X + (r >> 5) * 16384 + swz_off(r & 31, kp)) =
                packh2(hv.x, hv.y);
        }
        if (tid < 64) {
            float2 lv = *(const float2*)(lpr + (size_t)(p * 64 + tid) * 2);
            *(uint32_t*)(S + OFF_X2 + (tid >> 5) * 1536 + (tid & 31) * 48) =
                packh2(lv.x, lv.y);
        }
        float c_arr[2][8];   // [tile][mt*4 + e*2 + row8]
#pragma unroll
        for (int t = 0; t < 2; t++)
#pragma unroll
            for (int mt = 0; mt < 2; mt++)
#pragma unroll
                for (int row8 = 0; row8 < 2; row8++) {
                    int gp = p * 64 + t * 32 + mt * 16 + g4 + row8 * 8;
                    float2 cv = *(const float2*)(c0 + (size_t)gp * 128 + ng * 8 + c2);
                    c_arr[t][mt * 4 + row8]     = cv.x;   // e=0
                    c_arr[t][mt * 4 + 2 + row8] = cv.y;   // e=1
                }
        __syncthreads();

        int par = 0;
        // ================= 12 supersteps (tiles A then B, one window) =====
        for (int st = 0; st < STEPS; st++) {
#pragma unroll
            for (int t = 0; t < 2; t++) {
                const uint32_t abase = Sb + OFF_X + (uint32_t)t * 16384 +
                                       (uint32_t)par * 8192 + arowoff;
                const uint32_t xw    = OFF_X + (uint32_t)t * 16384 +
                                       (uint32_t)(par ^ 1) * 8192;
                const uint32_t x2b   = Sb + OFF_X2 + (uint32_t)t * 1536 + x2lane;

                // ---- GEMM: gates = [h | rx,ry,1] @ [Whh | wx,wy,bz]^T ----
                float acc[2][4][4];   // [mt][gate][frag]
#pragma unroll
                for (int mt = 0; mt < 2; mt++)
#pragma unroll
                    for (int nt = 0; nt < 4; nt++)
#pragma unroll
                        for (int j = 0; j < 4; j++) acc[mt][nt][j] = 0.f;

#pragma unroll
                for (int kk = 0; kk < KK_STEPS; kk++) {
                    const uint32_t koff = (((uint32_t)(2 * kk) + asel) ^ ax_) << 4;
                    uint32_t a0[4], a1[4];
                    LDSM_X4(a0[0], a0[1], a0[2], a0[3], abase + koff);
                    LDSM_X4(a1[0], a1[1], a1[2], a1[3], abase + 4096 + koff);
                    const uint32_t bkoff = (((uint32_t)(2 * kk) + bk_) ^ ax_) << 4;
#pragma unroll
                    for (int t2 = 0; t2 < 2; t2++) {
                        uint32_t b0, b1, b2, b3;
                        LDSM_X4(b0, b1, b2, b3, bbase + (uint32_t)t2 * 4096 + bkoff);
                        MMA16816(acc[0][2 * t2],     a0[0], a0[1], a0[2], a0[3], b0, b1);
                        MMA16816(acc[0][2 * t2 + 1], a0[0], a0[1], a0[2], a0[3], b2, b3);
                        MMA16816(acc[1][2 * t2],     a1[0], a1[1], a1[2], a1[3], b0, b1);
                        MMA16816(acc[1][2 * t2 + 1], a1[0], a1[1], a1[2], a1[3], b2, b3);
                    }
                }
                {   // extra k16 step: rank-2 dec_in + bias (X2 @ W2^T)
                    uint32_t a0[4], a1[4];
                    LDSM_X4(a0[0], a0[1], a0[2], a0[3], x2b);
                    LDSM_X4(a1[0], a1[1], a1[2], a1[3], x2b + 768);   // rows 16-31
#pragma unroll
                    for (int t2 = 0; t2 < 2; t2++) {
                        uint32_t b0, b1, b2, b3;
                        LDSM_X4(b0, b1, b2, b3, w2base + (uint32_t)t2 * 768);
                        MMA16816(acc[0][2 * t2],     a0[0], a0[1], a0[2], a0[3], b0, b1);
                        MMA16816(acc[0][2 * t2 + 1], a0[0], a0[1], a0[2], a0[3], b2, b3);
                        MMA16816(acc[1][2 * t2],     a1[0], a1[1], a1[2], a1[3], b0, b1);
                        MMA16816(acc[1][2 * t2 + 1], a1[0], a1[1], a1[2], a1[3], b2, b3);
                    }
                }

                // ---- epilogue: activations; h -> other X buf; rel partials ----
#pragma unroll
                for (int mt = 0; mt < 2; mt++) {
                    float axs[2], ays[2];
                    axs[0] = ays[0] = axs[1] = ays[1] = 0.f;
#pragma unroll
                    for (int row8 = 0; row8 < 2; row8++) {
                        float hpair[2];
#pragma unroll
                        for (int e = 0; e < 2; e++) {
                            int reg = row8 * 2 + e;
                            float gi = acc[mt][0][reg];
                            float gf = acc[mt][1][reg];
                            float gg = acc[mt][2][reg];
                            float go = acc[mt][3][reg];
                            int ci = mt * 4 + e * 2 + row8;
                            float cc = siga(gf) * c_arr[t][ci] + siga(gi) * tanh_ap(gg);
                            c_arr[t][ci] = cc;
                            float h = siga(go) * tanh_ap(cc);
                            hpair[e] = h;
                            int ul = ng * 8 + c2 + e;
                            axs[row8] = fmaf(h, whp[ul],       axs[row8]);
                            ays[row8] = fmaf(h, whp[128 + ul], ays[row8]);
                        }
                        int r = mt * 16 + g4 + row8 * 8;
                        *(uint32_t*)(S + xw + swz_off(r, ng * 8 + c2)) =
                            packh2(hpair[0], hpair[1]);
                    }
                    // butterfly over the quad lanes (same peds, different units)
#pragma unroll
                    for (int row8 = 0; row8 < 2; row8++) {
                        float& ax = axs[row8];
                        float& ay = ays[row8];
                        ax += __shfl_xor_sync(~0u, ax, 1); ax += __shfl_xor_sync(~0u, ax, 2);
                        ay += __shfl_xor_sync(~0u, ay, 1); ay += __shfl_xor_sync(~0u, ay, 2);
                        if ((lane & 3) == 0) {
                            int r = t * 32 + mt * 16 + g4 + row8 * 8;
                            *(float2*)(part + r * 36 + ng * 2) = make_float2(ax, ay);
                        }
                    }
                }
            }
            __syncthreads();   // both tiles: X + part complete

            // ---- reduce: rel = sum over 16 N-groups + b_hp; out; X2 ----
            if (tid < 64) {
                const float4* pr = (const float4*)(part + tid * 36);
                float4 q0 = pr[0], q1 = pr[1], q2 = pr[2], q3 = pr[3];
                float4 q4 = pr[4], q5 = pr[5], q6 = pr[6], q7 = pr[7];
                float rx = q0.x + q0.z + q1.x + q1.z + q2.x + q2.z + q3.x + q3.z +
                           q4.x + q4.z + q5.x + q5.z + q6.x + q6.z + q7.x + q7.z + bhp[0];
                float ry = q0.y + q0.w + q1.y + q1.w + q2.y + q2.w + q3.y + q3.w +
                           q4.y + q4.w + q5.y + q5.w + q6.y + q6.w + q7.y + q7.w + bhp[1];
                out[(size_t)st * 65536 + p * 64 + tid] = make_float2(rx, ry);
                *(uint32_t*)(S + OFF_X2 + (tid >> 5) * 1536 + (tid & 31) * 48) =
                    packh2(rx, ry);
            }
            __syncthreads();   // X2 ready for next superstep
            par ^= 1;
        }
    }
}

extern "C" void kernel_launch(void* const* d_in, const int* in_sizes, int n_in,
                              void* d_out, int out_size) {
    (void)in_sizes; (void)n_in; (void)out_size;
    const float* lpr  = (const float*)d_in[1];
    const float* h0   = (const float*)d_in[2];
    const float* c0   = (const float*)d_in[3];
    const float* w_ih = (const float*)d_in[4];
    const float* w_hh = (const float*)d_in[5];
    const float* b_ih = (const float*)d_in[6];
    const float* b_hh = (const float*)d_in[7];
    const float* w_se = (const float*)d_in[8];
    const float* b_se = (const float*)d_in[9];
    const float* w_hp = (const float*)d_in[10];
    const float* b_hp = (const float*)d_in[11];

    cudaFuncSetAttribute(decoder_mma, cudaFuncAttributeMaxDynamicSharedMemorySize, SMEM_BYTES);
    decoder_mma<<<GRID, THREADS, SMEM_BYTES>>>(lpr, h0, c0, w_ih, w_hh, b_ih, b_hh,
                                               w_se, b_se, w_hp, b_hp, (float2*)d_out);
}